// round 2
// baseline (speedup 1.0000x reference)
#include <cuda_runtime.h>

#define NN 100000
#define NE 3200000

// ---------------- device scratch (no dynamic allocation allowed) ----------------
__device__ int2   g_edges[NE];      // (src, norm-as-float-bits), CSR by dst
__device__ int    g_src[NE];
__device__ int    g_dst[NE];
__device__ int    g_cnt[NN];
__device__ int    g_rowptr[NN + 1];
__device__ int    g_cursor[NN];
__device__ int    g_bsum[128];
__device__ int    g_bsumEx[128];
__device__ float  g_dinv[NN];
__device__ float4 g_bufA[NN * 4];   // xw  -> (reused) H
__device__ float4 g_bufC[NN * 4];   // xw2
__device__ float4 g_x1[NN * 4];
__device__ float4 g_x2[NN * 4];

// ---------------- small helpers ----------------
__device__ __forceinline__ float sigm_f(float x) {
    return __fdividef(1.0f, 1.0f + __expf(-x));
}
__device__ __forceinline__ float tanh_f(float x) {
    float e = __expf(2.0f * x);
    return 1.0f - __fdividef(2.0f, e + 1.0f);
}
__device__ __forceinline__ float dot4(float4 w, float4 x) {
    return w.x * x.x + w.y * x.y + w.z * x.z + w.w * x.w;
}
__device__ __forceinline__ void fma4(float* a, float w, float4 v) {
    a[0] += w * v.x; a[1] += w * v.y; a[2] += w * v.z; a[3] += w * v.w;
}

// ---------------- graph preprocessing ----------------
__global__ void k_zero() {
    int i = blockIdx.x * blockDim.x + threadIdx.x;
    if (i < NN) g_cnt[i] = 0;
}

__global__ void k_count(const int* __restrict__ ei, int is64) {
    int e = blockIdx.x * blockDim.x + threadIdx.x;
    if (e >= NE) return;
    int s, d;
    if (is64) {  // int64 little-endian: low word holds the value
        s = ei[2 * e];
        d = ei[2 * (NE + e)];
    } else {
        s = ei[e];
        d = ei[NE + e];
    }
    g_src[e] = s; g_dst[e] = d;
    atomicAdd(&g_cnt[d], 1);
}

__global__ void k_dinv() {
    int i = blockIdx.x * blockDim.x + threadIdx.x;
    if (i < NN) g_dinv[i] = rsqrtf((float)g_cnt[i] + 1.0f);
}

__global__ void k_scanA() {
    __shared__ int sh[1024];
    int i = blockIdx.x * 1024 + threadIdx.x;
    int v = (i < NN) ? g_cnt[i] : 0;
    sh[threadIdx.x] = v;
    __syncthreads();
    #pragma unroll
    for (int off = 1; off < 1024; off <<= 1) {
        int t = (threadIdx.x >= off) ? sh[threadIdx.x - off] : 0;
        __syncthreads();
        sh[threadIdx.x] += t;
        __syncthreads();
    }
    if (i < NN) g_rowptr[i] = sh[threadIdx.x] - v;  // exclusive
    if (threadIdx.x == 1023) g_bsum[blockIdx.x] = sh[1023];
}

__global__ void k_scanB(int nb) {
    __shared__ int sh[128];
    int t = threadIdx.x;
    int v = (t < nb) ? g_bsum[t] : 0;
    sh[t] = v;
    __syncthreads();
    #pragma unroll
    for (int off = 1; off < 128; off <<= 1) {
        int tv = (t >= off) ? sh[t - off] : 0;
        __syncthreads();
        sh[t] += tv;
        __syncthreads();
    }
    g_bsumEx[t] = sh[t] - v;  // exclusive
}

__global__ void k_scanC() {
    int i = blockIdx.x * blockDim.x + threadIdx.x;
    if (i < NN) {
        int r = g_rowptr[i] + g_bsumEx[i >> 10];
        g_rowptr[i] = r;
        g_cursor[i] = r;
    }
    if (i == 0) g_rowptr[NN] = NE;
}

__global__ void k_scatter() {
    int e = blockIdx.x * blockDim.x + threadIdx.x;
    if (e >= NE) return;
    int s = g_src[e], d = g_dst[e];
    int p = atomicAdd(&g_cursor[d], 1);
    g_edges[p] = make_int2(s, __float_as_int(g_dinv[s] * g_dinv[d]));
}

// ---------------- GEMM1: xw = x[100000,512] @ W1[512,16] ----------------
__global__ void __launch_bounds__(256) k_gemm1(const float4* __restrict__ x4,
                                               const float4* __restrict__ w4) {
    __shared__ float  xs[256][33];   // padded, conflict-free
    __shared__ float4 ws[32][4];
    int tid = threadIdx.x;
    int row = blockIdx.x * 256 + tid;
    float acc[16];
    #pragma unroll
    for (int i = 0; i < 16; i++) acc[i] = 0.0f;

    for (int kc = 0; kc < 16; kc++) {
        #pragma unroll
        for (int j = 0; j < 8; j++) {
            int idx = j * 256 + tid;            // 0..2047 float4 slots
            int r = idx >> 3, c4 = idx & 7;
            int gr = blockIdx.x * 256 + r;
            float4 v = (gr < NN) ? x4[gr * 128 + kc * 8 + c4]
                                 : make_float4(0.f, 0.f, 0.f, 0.f);
            xs[r][c4 * 4 + 0] = v.x; xs[r][c4 * 4 + 1] = v.y;
            xs[r][c4 * 4 + 2] = v.z; xs[r][c4 * 4 + 3] = v.w;
        }
        if (tid < 128) ws[tid >> 2][tid & 3] = w4[(kc * 32 + (tid >> 2)) * 4 + (tid & 3)];
        __syncthreads();
        #pragma unroll
        for (int k = 0; k < 32; k++) {
            float xv = xs[tid][k];
            fma4(acc + 0,  xv, ws[k][0]);
            fma4(acc + 4,  xv, ws[k][1]);
            fma4(acc + 8,  xv, ws[k][2]);
            fma4(acc + 12, xv, ws[k][3]);
        }
        __syncthreads();
    }
    if (row < NN) {
        g_bufA[row * 4 + 0] = make_float4(acc[0],  acc[1],  acc[2],  acc[3]);
        g_bufA[row * 4 + 1] = make_float4(acc[4],  acc[5],  acc[6],  acc[7]);
        g_bufA[row * 4 + 2] = make_float4(acc[8],  acc[9],  acc[10], acc[11]);
        g_bufA[row * 4 + 3] = make_float4(acc[12], acc[13], acc[14], acc[15]);
    }
}

// ---------------- GCN aggregation (CSR, atomic-free) with fused epilogues --------
// MODE 0: in=g_bufA -> x1 = relu(agg+b1) -> g_x1 ; y = x1@W2 -> g_bufC
// MODE 1: in=g_bufC -> x2 = relu(agg+b2) -> g_x2
// MODE 2: in=g_bufA -> logits = agg@lin_w + lin_b -> log_softmax -> outp
template <int MODE>
__global__ void __launch_bounds__(256) k_agg(float* __restrict__ outp,
                                             const float* __restrict__ bias,
                                             const float4* __restrict__ W4,
                                             const float* __restrict__ Wb) {
    __shared__ float4 sW[160];
    if (MODE == 0) { if (threadIdx.x < 64)  sW[threadIdx.x] = W4[threadIdx.x]; }
    if (MODE == 2) { if (threadIdx.x < 160) sW[threadIdx.x] = W4[threadIdx.x]; }
    __syncthreads();

    int n = blockIdx.x * 256 + threadIdx.x;
    if (n >= NN) return;
    const float4* in4 = (MODE == 1) ? g_bufC : g_bufA;

    float dd = g_dinv[n]; dd *= dd;
    float acc[16];
    {
        float4 a0 = in4[n * 4 + 0], a1 = in4[n * 4 + 1];
        float4 a2 = in4[n * 4 + 2], a3 = in4[n * 4 + 3];
        acc[0] = dd * a0.x; acc[1] = dd * a0.y; acc[2]  = dd * a0.z; acc[3]  = dd * a0.w;
        acc[4] = dd * a1.x; acc[5] = dd * a1.y; acc[6]  = dd * a1.z; acc[7]  = dd * a1.w;
        acc[8] = dd * a2.x; acc[9] = dd * a2.y; acc[10] = dd * a2.z; acc[11] = dd * a2.w;
        acc[12]= dd * a3.x; acc[13]= dd * a3.y; acc[14] = dd * a3.z; acc[15] = dd * a3.w;
    }

    int beg = g_rowptr[n], end = g_rowptr[n + 1];
    #pragma unroll 2
    for (int e = beg; e < end; e++) {
        int2 ev = g_edges[e];
        int s = ev.x;
        float w = __int_as_float(ev.y);
        float4 v0 = in4[s * 4 + 0], v1 = in4[s * 4 + 1];
        float4 v2 = in4[s * 4 + 2], v3 = in4[s * 4 + 3];
        fma4(acc + 0,  w, v0);
        fma4(acc + 4,  w, v1);
        fma4(acc + 8,  w, v2);
        fma4(acc + 12, w, v3);
    }

    if (MODE == 0 || MODE == 1) {
        float xr[16];
        #pragma unroll
        for (int c = 0; c < 16; c++) xr[c] = fmaxf(acc[c] + __ldg(&bias[c]), 0.0f);
        float4* ox = (MODE == 0) ? (g_x1 + n * 4) : (g_x2 + n * 4);
        ox[0] = make_float4(xr[0],  xr[1],  xr[2],  xr[3]);
        ox[1] = make_float4(xr[4],  xr[5],  xr[6],  xr[7]);
        ox[2] = make_float4(xr[8],  xr[9],  xr[10], xr[11]);
        ox[3] = make_float4(xr[12], xr[13], xr[14], xr[15]);
        if (MODE == 0) {
            float y[16];
            #pragma unroll
            for (int i = 0; i < 16; i++) y[i] = 0.0f;
            #pragma unroll
            for (int k = 0; k < 16; k++) {
                fma4(y + 0,  xr[k], sW[k * 4 + 0]);
                fma4(y + 4,  xr[k], sW[k * 4 + 1]);
                fma4(y + 8,  xr[k], sW[k * 4 + 2]);
                fma4(y + 12, xr[k], sW[k * 4 + 3]);
            }
            g_bufC[n * 4 + 0] = make_float4(y[0],  y[1],  y[2],  y[3]);
            g_bufC[n * 4 + 1] = make_float4(y[4],  y[5],  y[6],  y[7]);
            g_bufC[n * 4 + 2] = make_float4(y[8],  y[9],  y[10], y[11]);
            g_bufC[n * 4 + 3] = make_float4(y[12], y[13], y[14], y[15]);
        }
    } else {  // MODE 2: logits + log_softmax
        float4 l[10];
        const float4* lb4 = (const float4*)Wb;
        #pragma unroll
        for (int c = 0; c < 10; c++) l[c] = lb4[c];
        #pragma unroll
        for (int k = 0; k < 16; k++) {
            float a = acc[k];
            #pragma unroll
            for (int c = 0; c < 10; c++) {
                float4 w = sW[k * 10 + c];
                l[c].x += a * w.x; l[c].y += a * w.y;
                l[c].z += a * w.z; l[c].w += a * w.w;
            }
        }
        float m = -1e30f;
        #pragma unroll
        for (int c = 0; c < 10; c++) {
            m = fmaxf(m, fmaxf(fmaxf(l[c].x, l[c].y), fmaxf(l[c].z, l[c].w)));
        }
        float ssum = 0.0f;
        #pragma unroll
        for (int c = 0; c < 10; c++) {
            ssum += __expf(l[c].x - m) + __expf(l[c].y - m)
                  + __expf(l[c].z - m) + __expf(l[c].w - m);
        }
        float lse = m + __logf(ssum);
        float4* o4 = (float4*)outp + n * 10;
        #pragma unroll
        for (int c = 0; c < 10; c++) {
            o4[c] = make_float4(l[c].x - lse, l[c].y - lse, l[c].z - lse, l[c].w - lse);
        }
    }
}

// ---------------- JumpingKnowledge bidirectional LSTM + attention ----------------
__global__ void __launch_bounds__(128, 4) k_lstm(
    const float4* __restrict__ wihf, const float4* __restrict__ whhf, const float* __restrict__ bf,
    const float4* __restrict__ wihb, const float4* __restrict__ whhb, const float* __restrict__ bb,
    const float* __restrict__ aw, const float* __restrict__ ab) {
    __shared__ float4 sif[512];    // w_ih_f [128,16]
    __shared__ float4 shf[1024];   // w_hh_f [128,32]
    __shared__ float4 sib[512];
    __shared__ float4 shb[1024];
    for (int i = threadIdx.x; i < 512; i += 128)  { sif[i] = wihf[i]; sib[i] = wihb[i]; }
    for (int i = threadIdx.x; i < 1024; i += 128) { shf[i] = whhf[i]; shb[i] = whhb[i]; }
    __syncthreads();

    int n = blockIdx.x * 128 + threadIdx.x;
    if (n >= NN) return;

    float4 xa[4], xb[4];
    #pragma unroll
    for (int q = 0; q < 4; q++) { xa[q] = g_x1[n * 4 + q]; xb[q] = g_x2[n * 4 + q]; }

    float h[32], c[32];
    float s0 = 0.0f, s1 = 0.0f;

    // forward cell t=0 (input x1, zero state)
    #pragma unroll 1
    for (int j = 0; j < 32; j++) {
        float gi = __ldg(bf + j), gg = __ldg(bf + 64 + j), go = __ldg(bf + 96 + j);
        #pragma unroll
        for (int q = 0; q < 4; q++) {
            gi += dot4(sif[j * 4 + q],        xa[q]);
            gg += dot4(sif[(64 + j) * 4 + q], xa[q]);
            go += dot4(sif[(96 + j) * 4 + q], xa[q]);
        }
        float cv = sigm_f(gi) * tanh_f(gg);
        c[j] = cv;
        float hv = sigm_f(go) * tanh_f(cv);
        h[j] = hv;
        s0 += hv * __ldg(aw + j);
    }
    // forward cell t=1 (input x2, state h,c)
    #pragma unroll 1
    for (int j = 0; j < 32; j++) {
        float gi = __ldg(bf + j),      gf = __ldg(bf + 32 + j);
        float gg = __ldg(bf + 64 + j), go = __ldg(bf + 96 + j);
        #pragma unroll
        for (int q = 0; q < 4; q++) {
            gi += dot4(sif[j * 4 + q],        xb[q]);
            gf += dot4(sif[(32 + j) * 4 + q], xb[q]);
            gg += dot4(sif[(64 + j) * 4 + q], xb[q]);
            go += dot4(sif[(96 + j) * 4 + q], xb[q]);
        }
        #pragma unroll
        for (int q = 0; q < 8; q++) {
            float4 wI = shf[j * 8 + q],        wF = shf[(32 + j) * 8 + q];
            float4 wG = shf[(64 + j) * 8 + q], wO = shf[(96 + j) * 8 + q];
            float h0 = h[q * 4 + 0], h1 = h[q * 4 + 1], h2 = h[q * 4 + 2], h3 = h[q * 4 + 3];
            gi += wI.x * h0 + wI.y * h1 + wI.z * h2 + wI.w * h3;
            gf += wF.x * h0 + wF.y * h1 + wF.z * h2 + wF.w * h3;
            gg += wG.x * h0 + wG.y * h1 + wG.z * h2 + wG.w * h3;
            go += wO.x * h0 + wO.y * h1 + wO.z * h2 + wO.w * h3;
        }
        float cv = sigm_f(gf) * c[j] + sigm_f(gi) * tanh_f(gg);
        float hv = sigm_f(go) * tanh_f(cv);
        s1 += hv * __ldg(aw + j);
    }
    // backward cell t=1 (input x2, zero state)
    #pragma unroll 1
    for (int j = 0; j < 32; j++) {
        float gi = __ldg(bb + j), gg = __ldg(bb + 64 + j), go = __ldg(bb + 96 + j);
        #pragma unroll
        for (int q = 0; q < 4; q++) {
            gi += dot4(sib[j * 4 + q],        xb[q]);
            gg += dot4(sib[(64 + j) * 4 + q], xb[q]);
            go += dot4(sib[(96 + j) * 4 + q], xb[q]);
        }
        float cv = sigm_f(gi) * tanh_f(gg);
        c[j] = cv;
        float hv = sigm_f(go) * tanh_f(cv);
        h[j] = hv;
        s1 += hv * __ldg(aw + 32 + j);
    }
    // backward cell t=0 (input x1, state h,c)
    #pragma unroll 1
    for (int j = 0; j < 32; j++) {
        float gi = __ldg(bb + j),      gf = __ldg(bb + 32 + j);
        float gg = __ldg(bb + 64 + j), go = __ldg(bb + 96 + j);
        #pragma unroll
        for (int q = 0; q < 4; q++) {
            gi += dot4(sib[j * 4 + q],        xa[q]);
            gf += dot4(sib[(32 + j) * 4 + q], xa[q]);
            gg += dot4(sib[(64 + j) * 4 + q], xa[q]);
            go += dot4(sib[(96 + j) * 4 + q], xa[q]);
        }
        #pragma unroll
        for (int q = 0; q < 8; q++) {
            float4 wI = shb[j * 8 + q],        wF = shb[(32 + j) * 8 + q];
            float4 wG = shb[(64 + j) * 8 + q], wO = shb[(96 + j) * 8 + q];
            float h0 = h[q * 4 + 0], h1 = h[q * 4 + 1], h2 = h[q * 4 + 2], h3 = h[q * 4 + 3];
            gi += wI.x * h0 + wI.y * h1 + wI.z * h2 + wI.w * h3;
            gf += wF.x * h0 + wF.y * h1 + wF.z * h2 + wF.w * h3;
            gg += wG.x * h0 + wG.y * h1 + wG.z * h2 + wG.w * h3;
            go += wO.x * h0 + wO.y * h1 + wO.z * h2 + wO.w * h3;
        }
        float cv = sigm_f(gf) * c[j] + sigm_f(gi) * tanh_f(gg);
        float hv = sigm_f(go) * tanh_f(cv);
        s0 += hv * __ldg(aw + 32 + j);
    }

    float abv = __ldg(ab);
    s0 += abv; s1 += abv;
    float m = fmaxf(s0, s1);
    float e0 = __expf(s0 - m), e1 = __expf(s1 - m);
    float inv = __fdividef(1.0f, e0 + e1);
    float a0 = e0 * inv, a1 = e1 * inv;
    #pragma unroll
    for (int q = 0; q < 4; q++) {
        float4 o;
        o.x = a0 * xa[q].x + a1 * xb[q].x;
        o.y = a0 * xa[q].y + a1 * xb[q].y;
        o.z = a0 * xa[q].z + a1 * xb[q].z;
        o.w = a0 * xa[q].w + a1 * xb[q].w;
        g_bufA[n * 4 + q] = o;
    }
}

// ---------------- launch ----------------
extern "C" void kernel_launch(void* const* d_in, const int* in_sizes, int n_in,
                              void* d_out, int out_size) {
    // input order: x, edge_index, W1, b1, W2, b2, w_ih_f, w_hh_f, b_f,
    //              w_ih_b, w_hh_b, b_b, att_w, att_b, lin_w, lin_b
    int is64 = (in_sizes[1] >= 4 * NE) ? 1 : 0;  // int64 stored as 2x int32 elements

    const int NB_N   = (NN + 255) / 256;
    const int NB_E   = (NE + 255) / 256;
    const int NB_SC  = (NN + 1023) / 1024;

    k_zero<<<NB_N, 256>>>();
    k_count<<<NB_E, 256>>>((const int*)d_in[1], is64);
    k_dinv<<<NB_N, 256>>>();
    k_scanA<<<NB_SC, 1024>>>();
    k_scanB<<<1, 128>>>(NB_SC);
    k_scanC<<<NB_N, 256>>>();
    k_scatter<<<NB_E, 256>>>();

    k_gemm1<<<NB_N, 256>>>((const float4*)d_in[0], (const float4*)d_in[2]);

    k_agg<0><<<NB_N, 256>>>(nullptr, (const float*)d_in[3], (const float4*)d_in[4], nullptr);
    k_agg<1><<<NB_N, 256>>>(nullptr, (const float*)d_in[5], nullptr, nullptr);

    k_lstm<<<(NN + 127) / 128, 128>>>(
        (const float4*)d_in[6], (const float4*)d_in[7], (const float*)d_in[8],
        (const float4*)d_in[9], (const float4*)d_in[10], (const float*)d_in[11],
        (const float*)d_in[12], (const float*)d_in[13]);

    k_agg<2><<<NB_N, 256>>>((float*)d_out, nullptr, (const float4*)d_in[14],
                            (const float*)d_in[15]);
}